// round 13
// baseline (speedup 1.0000x reference)
#include <cuda_runtime.h>
#include <math.h>

#define Bsz 64
#define Tsz 2048
#define Dsz 256
#define Hsz 512
#define Gsz 2048
#define NB  128
#define GRP 64

typedef unsigned long long u64;

// ---- packed fp32x2 helpers (Blackwell FFMA2, PTX-only) ----
__device__ __forceinline__ u64 ffma2(u64 a, u64 b, u64 c) {
    u64 d;
    asm("fma.rn.f32x2 %0, %1, %2, %3;" : "=l"(d) : "l"(a), "l"(b), "l"(c));
    return d;
}
__device__ __forceinline__ u64 dup2(float x) {
    u64 d;
    asm("mov.b64 %0, {%1, %1};" : "=l"(d) : "r"(__float_as_uint(x)));
    return d;
}

// Scratch (device globals)
__device__ float g_Up[64 * Hsz * 32];              // [cg][k(512)][c(32)]  4 MB
__device__ float g_Wp[64 * Dsz * 32];              // [cg][k(256)][c(32)]  2 MB
__device__ float g_h[2 * Hsz * Bsz];               // [parity][j][b]
__device__ unsigned g_cnt2[64];                    // 2 counters, 128B apart

__global__ void reset_bar_k() { if (threadIdx.x < 64) g_cnt2[threadIdx.x] = 0u; }

// g_Up[cg][k][c] = U[k][gate*512 + cg*8 + jj], c = gate*8 + jj  (32 cols per cg)
__global__ void pack_U_k(const float* __restrict__ U) {
    int idx = blockIdx.x * blockDim.x + threadIdx.x;   // 2^20 total
    int c  = idx & 31;
    int k  = (idx >> 5) & (Hsz - 1);
    int cg = idx >> 14;
    g_Up[idx] = U[k * Gsz + (c >> 3) * Hsz + cg * 8 + (c & 7)];
}

// g_Wp[cg][k][c] = W[k][gate*512 + cg*8 + jj], k in [0,256)
__global__ void pack_W_k(const float* __restrict__ W) {
    int idx = blockIdx.x * blockDim.x + threadIdx.x;   // 2^19 total
    int c  = idx & 31;
    int k  = (idx >> 5) & (Dsz - 1);
    int cg = idx >> 13;
    g_Wp[idx] = W[k * Gsz + (c >> 3) * Hsz + cg * 8 + (c & 7)];
}

// ---- dual 64-CTA group barriers: release-REDG arrive + acquire-poll wait ----
__device__ __forceinline__ void garrive(int g) {
    __syncthreads();
    if (threadIdx.x == 0) {
        asm volatile("red.release.gpu.add.u32 [%0], %1;" :: "l"(&g_cnt2[g * 32]), "r"(1u) : "memory");
    }
}
__device__ __forceinline__ void gwait(int g, unsigned target) {
    if (threadIdx.x == 0) {
        unsigned v;
        do {
            asm volatile("ld.acquire.gpu.u32 %0, [%1];" : "=r"(v) : "l"(&g_cnt2[g * 32]) : "memory");
        } while (v < target);
    }
    __syncthreads();
}

// Persistent recurrence with FUSED input projection (no separate GEMM, no g_xw).
// 128 CTAs = (b-half bh) x (64 col-groups cg: 8 hidden units = 32 gate cols).
// Resident in smem: U slice [512][32] (64KB) + W slice [256][32] (32KB).
// Per step, BEFORE the barrier wait: warp w stages x[:, t, 32w:32w+32) for its
// half's 32 batches into xs (warp-private rows, conflict-free STS) and
// accumulates the xW partial into acc — this fills the former idle wait window.
// After gwait: unchanged R12 recurrence (warp w owns h-k in [64w,64w+64),
// double-halved warp-local staging, 8b x 4c lane tile, 16 FFMA2/k).
// Single partial store covers xW+h; fused reduce + bias + activation.
// Smem floats: Us 16384 + Ws 8192 + hs 16384 + xs 8192 + part 8192 = 57344 (224KB).
#define REC_SMEM_FLOATS (16384 + 8192 + 16384 + 8192 + 8192)

__global__ __launch_bounds__(256, 1) void lstm_rec_k(float* __restrict__ out,
                                                     const float* __restrict__ x,
                                                     const float* __restrict__ bias) {
    extern __shared__ float sm[];
    float* Us   = sm;            // [512][32]
    float* Ws   = sm + 16384;    // [256][32]
    float* hs   = sm + 24576;    // [w][64][32]
    float* xs   = sm + 40960;    // [256][32]  (k rows, 32 batches of this half)
    float* part = sm + 49152;    // [w][32c][32b]

    const int n   = blockIdx.x;
    const int tid = threadIdx.x;
    const int bh  = n & 1;
    const int cg  = n >> 1;
    const int w   = tid >> 5;
    const int L   = tid & 31;
    const int b0  = (L & 3) * 8;
    const int c0  = (L >> 2) * 4;
    const int ub  = tid & 31;          // update role: batch within half
    const int ujj = tid >> 5;          // update role: hidden-within-cg 0..7
    const int jbase = cg * 8;

    // resident U slice [512][32] and W slice [256][32]
    {
        const float4* Usrc = (const float4*)(g_Up + (size_t)cg * 16384);
        float4* Udst = (float4*)Us;
        for (int i = tid; i < 4096; i += 256) Udst[i] = Usrc[i];
        const float4* Wsrc = (const float4*)(g_Wp + (size_t)cg * 8192);
        float4* Wdst = (float4*)Ws;
        for (int i = tid; i < 2048; i += 256) Wdst[i] = Wsrc[i];
    }

    // bias for this thread's update role (4 gates)
    const float bj0 = bias[0 * Hsz + jbase + ujj];
    const float bj1 = bias[1 * Hsz + jbase + ujj];
    const float bj2 = bias[2 * Hsz + jbase + ujj];
    const float bj3 = bias[3 * Hsz + jbase + ujj];

    // zero h parity 0 (this CTA's slice)
    g_h[(jbase + ujj) * 64 + bh * 32 + ub] = 0.0f;
    float creg = 0.0f, hreg = 0.0f;

    unsigned target = GRP;
    garrive(bh);

    float* hw = hs + w * 2048;         // this warp's h staging area [64][32]
    // x row base for this lane's batch (b = bh*32 + L), k offset = 32w
    const float* xrow = x + ((size_t)(bh * 32 + L) * Tsz) * Dsz + 32 * w;

    for (int step = 0; step < Tsz; ++step) {
        const int p = step & 1;
        const float* hq = g_h + p * (Hsz * Bsz) + bh * 32;   // row stride 64

        u64 acc[16];
#pragma unroll
        for (int j = 0; j < 16; ++j) acc[j] = 0ull;

        // ===== pre-wait: stage x slice (warp-private rows) + xW partial =====
        {
            const float* xp = xrow + (size_t)step * Dsz;
            float4 xv[8];
#pragma unroll
            for (int m = 0; m < 8; ++m)
                xv[m] = __ldg((const float4*)(xp + 4 * m));
#pragma unroll
            for (int m = 0; m < 8; ++m) {
                const int k = 32 * w + 4 * m;
                xs[(k + 0) * 32 + L] = xv[m].x;
                xs[(k + 1) * 32 + L] = xv[m].y;
                xs[(k + 2) * 32 + L] = xv[m].z;
                xs[(k + 3) * 32 + L] = xv[m].w;
            }
        }
        __syncwarp();

#pragma unroll 16
        for (int i = 0; i < 32; ++i) {
            const int k = 32 * w + i;
            ulonglong2 hA = *(const ulonglong2*)&xs[k * 32 + b0];
            ulonglong2 hB = *(const ulonglong2*)&xs[k * 32 + b0 + 4];
            float4 uq = *(const float4*)&Ws[k * 32 + c0];
            u64 u0 = dup2(uq.x), u1 = dup2(uq.y), u2 = dup2(uq.z), u3 = dup2(uq.w);
            acc[0]  = ffma2(hA.x, u0, acc[0]);
            acc[1]  = ffma2(hA.y, u0, acc[1]);
            acc[2]  = ffma2(hB.x, u0, acc[2]);
            acc[3]  = ffma2(hB.y, u0, acc[3]);
            acc[4]  = ffma2(hA.x, u1, acc[4]);
            acc[5]  = ffma2(hA.y, u1, acc[5]);
            acc[6]  = ffma2(hB.x, u1, acc[6]);
            acc[7]  = ffma2(hB.y, u1, acc[7]);
            acc[8]  = ffma2(hA.x, u2, acc[8]);
            acc[9]  = ffma2(hA.y, u2, acc[9]);
            acc[10] = ffma2(hB.x, u2, acc[10]);
            acc[11] = ffma2(hB.y, u2, acc[11]);
            acc[12] = ffma2(hA.x, u3, acc[12]);
            acc[13] = ffma2(hA.y, u3, acc[13]);
            acc[14] = ffma2(hB.x, u3, acc[14]);
            acc[15] = ffma2(hB.y, u3, acc[15]);
        }

        // ===== wait for previous step's h =====
        gwait(bh, target);
        target += GRP;

        // ---- stage h half A (rows [64w, 64w+32)) ----
        float4 pv[8];
#pragma unroll
        for (int m = 0; m < 8; ++m) {
            int idx = L + 32 * m; int r = idx >> 3, q = idx & 7;
            pv[m] = __ldcg((const float4*)(hq + (w * 64 + r) * 64) + q);
        }
#pragma unroll
        for (int m = 0; m < 8; ++m) {
            int idx = L + 32 * m; int r = idx >> 3, q = idx & 7;
            *(float4*)&hw[r * 32 + q * 4] = pv[m];
        }
        // issue LDG for half B (latency hides under compute A)
        float4 pw[8];
#pragma unroll
        for (int m = 0; m < 8; ++m) {
            int idx = L + 32 * m; int r = 32 + (idx >> 3), q = idx & 7;
            pw[m] = __ldcg((const float4*)(hq + (w * 64 + r) * 64) + q);
        }
        __syncwarp();

        // ---- compute h half A ----
#pragma unroll 16
        for (int i = 0; i < 32; ++i) {
            ulonglong2 hA = *(const ulonglong2*)&hw[i * 32 + b0];
            ulonglong2 hB = *(const ulonglong2*)&hw[i * 32 + b0 + 4];
            float4 uq = *(const float4*)&Us[(w * 64 + i) * 32 + c0];
            u64 u0 = dup2(uq.x), u1 = dup2(uq.y), u2 = dup2(uq.z), u3 = dup2(uq.w);
            acc[0]  = ffma2(hA.x, u0, acc[0]);
            acc[1]  = ffma2(hA.y, u0, acc[1]);
            acc[2]  = ffma2(hB.x, u0, acc[2]);
            acc[3]  = ffma2(hB.y, u0, acc[3]);
            acc[4]  = ffma2(hA.x, u1, acc[4]);
            acc[5]  = ffma2(hA.y, u1, acc[5]);
            acc[6]  = ffma2(hB.x, u1, acc[6]);
            acc[7]  = ffma2(hB.y, u1, acc[7]);
            acc[8]  = ffma2(hA.x, u2, acc[8]);
            acc[9]  = ffma2(hA.y, u2, acc[9]);
            acc[10] = ffma2(hB.x, u2, acc[10]);
            acc[11] = ffma2(hB.y, u2, acc[11]);
            acc[12] = ffma2(hA.x, u3, acc[12]);
            acc[13] = ffma2(hA.y, u3, acc[13]);
            acc[14] = ffma2(hB.x, u3, acc[14]);
            acc[15] = ffma2(hB.y, u3, acc[15]);
        }

        // ---- stage h half B ----
#pragma unroll
        for (int m = 0; m < 8; ++m) {
            int idx = L + 32 * m; int r = 32 + (idx >> 3), q = idx & 7;
            *(float4*)&hw[r * 32 + q * 4] = pw[m];
        }
        __syncwarp();

        // ---- compute h half B ----
#pragma unroll 16
        for (int i = 32; i < 64; ++i) {
            ulonglong2 hA = *(const ulonglong2*)&hw[i * 32 + b0];
            ulonglong2 hB = *(const ulonglong2*)&hw[i * 32 + b0 + 4];
            float4 uq = *(const float4*)&Us[(w * 64 + i) * 32 + c0];
            u64 u0 = dup2(uq.x), u1 = dup2(uq.y), u2 = dup2(uq.z), u3 = dup2(uq.w);
            acc[0]  = ffma2(hA.x, u0, acc[0]);
            acc[1]  = ffma2(hA.y, u0, acc[1]);
            acc[2]  = ffma2(hB.x, u0, acc[2]);
            acc[3]  = ffma2(hB.y, u0, acc[3]);
            acc[4]  = ffma2(hA.x, u1, acc[4]);
            acc[5]  = ffma2(hA.y, u1, acc[5]);
            acc[6]  = ffma2(hB.x, u1, acc[6]);
            acc[7]  = ffma2(hB.y, u1, acc[7]);
            acc[8]  = ffma2(hA.x, u2, acc[8]);
            acc[9]  = ffma2(hA.y, u2, acc[9]);
            acc[10] = ffma2(hB.x, u2, acc[10]);
            acc[11] = ffma2(hB.y, u2, acc[11]);
            acc[12] = ffma2(hA.x, u3, acc[12]);
            acc[13] = ffma2(hA.y, u3, acc[13]);
            acc[14] = ffma2(hB.x, u3, acc[14]);
            acc[15] = ffma2(hB.y, u3, acc[15]);
        }

        // per-warp partial tile [32c][32b] (xW + h combined)
#pragma unroll
        for (int j = 0; j < 4; ++j) {
            float* pp = part + w * 1024 + (c0 + j) * 32 + b0;
            *(ulonglong2*)pp       = make_ulonglong2(acc[4 * j + 0], acc[4 * j + 1]);
            *(ulonglong2*)(pp + 4) = make_ulonglong2(acc[4 * j + 2], acc[4 * j + 3]);
        }
        __syncthreads();

        // FUSED reduce + update: thread (b = ub, j = jbase + ujj) sums its own
        // 8 warp-partials per gate (bank = ub -> conflict-free scalar LDS)
        float v[4];
#pragma unroll
        for (int g = 0; g < 4; ++g) {
            const float* pp = part + (g * 8 + ujj) * 32 + ub;
            float s = pp[0];
#pragma unroll
            for (int ww = 1; ww < 8; ++ww) s += pp[ww * 1024];
            v[g] = s;
        }
        float ig = 1.0f / (1.0f + __expf(-(v[0] + bj0)));
        float fg = 1.0f / (1.0f + __expf(-(v[1] + bj1)));
        float gg = tanhf(v[2] + bj2);
        float og = 1.0f / (1.0f + __expf(-(v[3] + bj3)));
        creg = fg * creg + ig * gg;
        hreg = og * tanhf(creg);
        __stcg(&g_h[(p ^ 1) * (Hsz * Bsz) + (jbase + ujj) * 64 + bh * 32 + ub], hreg);

        garrive(bh);
    }

    out[(bh * 32 + ub) * Hsz + jbase + ujj] = hreg;
    out[Bsz * Hsz + (bh * 32 + ub) * Hsz + jbase + ujj] = creg;
}

extern "C" void kernel_launch(void* const* d_in, const int* in_sizes, int n_in,
                              void* d_out, int out_size) {
    const float* x    = (const float*)d_in[0];
    const float* W    = (const float*)d_in[1];
    const float* U    = (const float*)d_in[2];
    const float* bias = (const float*)d_in[3];
    float* out = (float*)d_out;
    (void)in_sizes; (void)n_in; (void)out_size;

    static int smem_set = 0;
    if (!smem_set) {
        cudaFuncSetAttribute(lstm_rec_k, cudaFuncAttributeMaxDynamicSharedMemorySize,
                             REC_SMEM_FLOATS * 4);
        smem_set = 1;
    }

    pack_U_k<<<2048, 512>>>(U);
    pack_W_k<<<1024, 512>>>(W);
    reset_bar_k<<<1, 64>>>();
    lstm_rec_k<<<NB, 256, REC_SMEM_FLOATS * 4>>>(out, x, bias);
}